// round 1
// baseline (speedup 1.0000x reference)
#include <cuda_runtime.h>
#include <cstdint>

#define NB_B   2
#define NB     512
#define LQ     64
#define KEYN   65
#define NH     8
#define HD     64
#define CDIM   512
#define NTOK   32768
#define BNB    (NB_B*NB)        // 1024 blocks total
#define MX     (NB_B*NTOK)      // 65536 x-rows
#define KVROWS (BNB*KEYN)       // 66560 kv-rows

// -------- device scratch (static, allocation-guard safe) --------
__device__ float g_q  [(size_t)MX*CDIM];
__device__ float g_k  [(size_t)KVROWS*CDIM];
__device__ float g_v  [(size_t)KVROWS*CDIM];
__device__ float g_bm [(size_t)BNB*CDIM];
__device__ float g_att[(size_t)MX*CDIM];

// ================= block mean =================
__global__ void mean_kernel(const float* __restrict__ x) {
    int blk = blockIdx.x;                      // 0..1023 (b*512+nb)
    const float* base = x + (size_t)blk * (LQ * CDIM);
    for (int c = threadIdx.x; c < CDIM; c += blockDim.x) {
        float s = 0.f;
        #pragma unroll 8
        for (int l = 0; l < LQ; l++) s += base[(size_t)l * CDIM + c];
        g_bm[(size_t)blk * CDIM + c] = s * (1.f / 64.f);
    }
}

// ================= tf32 mma helpers =================
__device__ __forceinline__ float to_tf32(float x) {
    uint32_t u;
    asm("cvt.rna.tf32.f32 %0, %1;" : "=r"(u) : "f"(x));
    return __uint_as_float(u);
}

__device__ __forceinline__ void mma_tf32(float* c, const float* a, const float* b) {
    const uint32_t* A = reinterpret_cast<const uint32_t*>(a);
    const uint32_t* Bv = reinterpret_cast<const uint32_t*>(b);
    asm volatile(
        "mma.sync.aligned.m16n8k8.row.col.f32.tf32.tf32.f32 "
        "{%0,%1,%2,%3}, {%4,%5,%6,%7}, {%8,%9}, {%0,%1,%2,%3};\n"
        : "+f"(c[0]), "+f"(c[1]), "+f"(c[2]), "+f"(c[3])
        : "r"(A[0]), "r"(A[1]), "r"(A[2]), "r"(A[3]),
          "r"(Bv[0]), "r"(Bv[1]));
}

// epilogue scatter
template <int MODE>
__device__ __forceinline__ void emit(int row, int col, float v, float* outp) {
    if (MODE == 0) {
        if (col < CDIM) {
            g_q[(size_t)row * CDIM + col] = v;
        } else {
            size_t kvr = (size_t)((row >> 6) * KEYN + (row & 63));
            if (col < 2 * CDIM) g_k[kvr * CDIM + (col - CDIM)] = v;
            else                g_v[kvr * CDIM + (col - 2 * CDIM)] = v;
        }
    } else if (MODE == 1) {
        size_t r = (size_t)row * KEYN + (KEYN - 1);
        if (col < CDIM) g_k[r * CDIM + col] = v;
        else            g_v[r * CDIM + (col - CDIM)] = v;
    } else {
        outp[(size_t)row * CDIM + col] = v;
    }
}

// ================= tf32 GEMM: C = A[M,512] * W[N,512]^T + bias =================
// 128x128x32 tiles, 256 threads = 8 warps (2x4), warp tile 64x32, mma m16n8k8
template <int MODE>
__global__ void __launch_bounds__(256) gemm_tf32(const float* __restrict__ Ain,
                                                 const float* __restrict__ W,
                                                 const float* __restrict__ bias,
                                                 float* __restrict__ outp) {
    const float* A = (MODE == 1) ? g_bm : (MODE == 2 ? g_att : Ain);
    __shared__ float As[128][36];
    __shared__ float Bs[128][36];

    int tid = threadIdx.x;
    int m0 = blockIdx.x * 128;
    int n0 = blockIdx.y * 128;
    int lr = tid >> 3;          // 0..31
    int lc = (tid & 7) * 4;     // 0..28

    int lane = tid & 31, wid = tid >> 5;
    int wm = wid >> 2, wn = wid & 3;   // warp grid 2 x 4
    int g = lane >> 2, t4 = lane & 3;

    float acc[4][4][4];
    #pragma unroll
    for (int mi = 0; mi < 4; mi++)
        #pragma unroll
        for (int ni = 0; ni < 4; ni++)
            #pragma unroll
            for (int r = 0; r < 4; r++) acc[mi][ni][r] = 0.f;

    float4 ra[4], rb[4];
    {
        #pragma unroll
        for (int i = 0; i < 4; i++) {
            ra[i] = *reinterpret_cast<const float4*>(&A[(size_t)(m0 + lr + 32 * i) * CDIM + 0 + lc]);
            rb[i] = *reinterpret_cast<const float4*>(&W[(size_t)(n0 + lr + 32 * i) * CDIM + 0 + lc]);
        }
    }

    for (int k0 = 0; k0 < CDIM; k0 += 32) {
        __syncthreads();
        #pragma unroll
        for (int i = 0; i < 4; i++) {
            float4 ta = make_float4(to_tf32(ra[i].x), to_tf32(ra[i].y), to_tf32(ra[i].z), to_tf32(ra[i].w));
            float4 tb = make_float4(to_tf32(rb[i].x), to_tf32(rb[i].y), to_tf32(rb[i].z), to_tf32(rb[i].w));
            *reinterpret_cast<float4*>(&As[lr + 32 * i][lc]) = ta;
            *reinterpret_cast<float4*>(&Bs[lr + 32 * i][lc]) = tb;
        }
        __syncthreads();
        if (k0 + 32 < CDIM) {
            #pragma unroll
            for (int i = 0; i < 4; i++) {
                ra[i] = *reinterpret_cast<const float4*>(&A[(size_t)(m0 + lr + 32 * i) * CDIM + (k0 + 32) + lc]);
                rb[i] = *reinterpret_cast<const float4*>(&W[(size_t)(n0 + lr + 32 * i) * CDIM + (k0 + 32) + lc]);
            }
        }
        #pragma unroll
        for (int kk = 0; kk < 32; kk += 8) {
            float afr[4][4], bfr[4][2];
            #pragma unroll
            for (int mi = 0; mi < 4; mi++) {
                int row = wm * 64 + mi * 16 + g;
                afr[mi][0] = As[row][kk + t4];
                afr[mi][1] = As[row + 8][kk + t4];
                afr[mi][2] = As[row][kk + t4 + 4];
                afr[mi][3] = As[row + 8][kk + t4 + 4];
            }
            #pragma unroll
            for (int ni = 0; ni < 4; ni++) {
                int col = wn * 32 + ni * 8 + g;
                bfr[ni][0] = Bs[col][kk + t4];
                bfr[ni][1] = Bs[col][kk + t4 + 4];
            }
            #pragma unroll
            for (int mi = 0; mi < 4; mi++)
                #pragma unroll
                for (int ni = 0; ni < 4; ni++)
                    mma_tf32(acc[mi][ni], afr[mi], bfr[ni]);
        }
    }

    // epilogue
    #pragma unroll
    for (int mi = 0; mi < 4; mi++) {
        #pragma unroll
        for (int ni = 0; ni < 4; ni++) {
            int row = m0 + wm * 64 + mi * 16 + g;
            int col = n0 + wn * 32 + ni * 8 + t4 * 2;
            float b0 = bias[col], b1 = bias[col + 1];
            emit<MODE>(row,     col,     acc[mi][ni][0] + b0, outp);
            emit<MODE>(row,     col + 1, acc[mi][ni][1] + b1, outp);
            emit<MODE>(row + 8, col,     acc[mi][ni][2] + b0, outp);
            emit<MODE>(row + 8, col + 1, acc[mi][ni][3] + b1, outp);
        }
    }
}

// ================= attention =================
// one CTA per (b, blk): 256 threads, loop over 8 heads
// smem floats: bias4 16640 | mask 4160 | q 64*68 | k 72*68 | v 65*68 | comb 64*68
#define SM_MASK_OFF 16640
#define SM_Q_OFF    20800
#define SM_K_OFF    (SM_Q_OFF + 64 * 68)
#define SM_V_OFF    (SM_K_OFF + 72 * 68)
#define SM_CB_OFF   (SM_V_OFF + 65 * 68)
#define ATTN_SMEM_FLOATS (SM_CB_OFF + 64 * 68)
#define ATTN_SMEM_BYTES  (ATTN_SMEM_FLOATS * 4)

__global__ void __launch_bounds__(256) attn_kernel(const float* __restrict__ edge,
                                                   const int* __restrict__ amask,
                                                   const float* __restrict__ eg_w,
                                                   const float* __restrict__ eg_b) {
    extern __shared__ float sm[];
    float4* sm_bias = reinterpret_cast<float4*>(sm);   // 4160 entries of 4 floats
    float* sm_mask = sm + SM_MASK_OFF;
    float* q_s = sm + SM_Q_OFF;
    float* k_s = sm + SM_K_OFF;
    float* v_s = sm + SM_V_OFF;
    float* cb_s = sm + SM_CB_OFF;

    int bid = blockIdx.x;      // 0..1023
    int tid = threadIdx.x;

    // preprocess bias (with diag / block-node overrides) and mask
    const float4* e4 = reinterpret_cast<const float4*>(edge) + (size_t)bid * 4160;
    const int* mk = amask + (size_t)bid * 4160;
    for (int i = tid; i < 4160; i += 256) {
        int q = i / 65;
        int k = i - q * 65;
        float4 e = e4[i];
        if (k == 64 || k == q) e = make_float4(0.f, 0.f, 0.f, 1.f);
        sm_bias[i] = e;
        sm_mask[i] = (mk[i] != 0) ? 1.f : 0.f;
    }
    // zero-pad k rows 65..71 (read by cols>=65 lanes, results discarded)
    for (int i = tid; i < 7 * 68; i += 256) k_s[65 * 68 + i] = 0.f;

    int lane = tid & 31, warp = tid >> 5;
    int t8 = lane & 7, g2 = lane >> 3;
    int r0 = warp * 8 + g2 * 2;          // this lane handles rows r0, r0+1

    for (int h = 0; h < NH; h++) {
        __syncthreads();
        // load q/k/v head slices
        for (int f = tid; f < 64 * 16; f += 256) {
            int row = f >> 4, c4 = (f & 15) * 4;
            *reinterpret_cast<float4*>(&q_s[row * 68 + c4]) =
                *reinterpret_cast<const float4*>(&g_q[(size_t)(bid * 64 + row) * CDIM + h * 64 + c4]);
        }
        for (int f = tid; f < 65 * 16; f += 256) {
            int row = f / 16, c4 = (f & 15) * 4;
            size_t src = (size_t)(bid * 65 + row) * CDIM + h * 64 + c4;
            *reinterpret_cast<float4*>(&k_s[row * 68 + c4]) =
                *reinterpret_cast<const float4*>(&g_k[src]);
            *reinterpret_cast<float4*>(&v_s[row * 68 + c4]) =
                *reinterpret_cast<const float4*>(&g_v[src]);
        }
        __syncthreads();

        float w0 = eg_w[h * 4 + 0], w1 = eg_w[h * 4 + 1];
        float w2 = eg_w[h * 4 + 2], w3 = eg_w[h * 4 + 3];
        float eb = eg_b[h];

        // ---- scores: rows r0,r0+1 x cols {t8+8j} ----
        float acc0[9], acc1[9];
        #pragma unroll
        for (int j = 0; j < 9; j++) { acc0[j] = 0.f; acc1[j] = 0.f; }
        #pragma unroll 4
        for (int d4 = 0; d4 < 16; d4++) {
            float4 qa = *reinterpret_cast<const float4*>(&q_s[r0 * 68 + d4 * 4]);
            float4 qb = *reinterpret_cast<const float4*>(&q_s[(r0 + 1) * 68 + d4 * 4]);
            #pragma unroll
            for (int j = 0; j < 9; j++) {
                float4 kv = *reinterpret_cast<const float4*>(&k_s[(t8 + 8 * j) * 68 + d4 * 4]);
                acc0[j] = fmaf(qa.x, kv.x, acc0[j]);
                acc0[j] = fmaf(qa.y, kv.y, acc0[j]);
                acc0[j] = fmaf(qa.z, kv.z, acc0[j]);
                acc0[j] = fmaf(qa.w, kv.w, acc0[j]);
                acc1[j] = fmaf(qb.x, kv.x, acc1[j]);
                acc1[j] = fmaf(qb.y, kv.y, acc1[j]);
                acc1[j] = fmaf(qb.z, kv.z, acc1[j]);
                acc1[j] = fmaf(qb.w, kv.w, acc1[j]);
            }
        }

        // ---- masked softmax + lew, write combined to smem ----
        #pragma unroll
        for (int rr = 0; rr < 2; rr++) {
            float* acc = rr ? acc1 : acc0;
            int row = r0 + rr;
            float mx = -1e30f;
            #pragma unroll
            for (int j = 0; j < 9; j++) {
                int col = t8 + 8 * j;
                if (col < 65) {
                    int idx = row * 65 + col;
                    float s = acc[j] * 0.125f + sm_bias[idx].w;
                    s = (sm_mask[idx] != 0.f) ? s : -1e30f;
                    acc[j] = s;
                    mx = fmaxf(mx, s);
                } else {
                    acc[j] = -1e30f;
                }
            }
            mx = fmaxf(mx, __shfl_xor_sync(0xffffffffu, mx, 1));
            mx = fmaxf(mx, __shfl_xor_sync(0xffffffffu, mx, 2));
            mx = fmaxf(mx, __shfl_xor_sync(0xffffffffu, mx, 4));
            float sum = 0.f;
            #pragma unroll
            for (int j = 0; j < 9; j++) {
                float p = __expf(acc[j] - mx);
                acc[j] = p;
                sum += p;
            }
            sum += __shfl_xor_sync(0xffffffffu, sum, 1);
            sum += __shfl_xor_sync(0xffffffffu, sum, 2);
            sum += __shfl_xor_sync(0xffffffffu, sum, 4);
            float inv = 1.f / sum;
            #pragma unroll
            for (int j = 0; j < 9; j++) {
                int col = t8 + 8 * j;
                if (col < 65) {
                    int idx = row * 65 + col;
                    float4 bz = sm_bias[idx];
                    float lew = (bz.x * w0 + bz.y * w1 + bz.z * w2 + bz.w * w3 + eb) * sm_mask[idx];
                    cb_s[row * 68 + col] = acc[j] * inv + lew;
                }
            }
        }
        __syncwarp();

        // ---- AV: out[row, d in t8*8 .. t8*8+7] ----
        float o0[8], o1[8];
        #pragma unroll
        for (int j = 0; j < 8; j++) { o0[j] = 0.f; o1[j] = 0.f; }
        for (int k = 0; k < 65; k++) {
            float cv0 = cb_s[r0 * 68 + k];
            float cv1 = cb_s[(r0 + 1) * 68 + k];
            float4 va = *reinterpret_cast<const float4*>(&v_s[k * 68 + t8 * 8]);
            float4 vb = *reinterpret_cast<const float4*>(&v_s[k * 68 + t8 * 8 + 4]);
            o0[0] = fmaf(cv0, va.x, o0[0]); o0[1] = fmaf(cv0, va.y, o0[1]);
            o0[2] = fmaf(cv0, va.z, o0[2]); o0[3] = fmaf(cv0, va.w, o0[3]);
            o0[4] = fmaf(cv0, vb.x, o0[4]); o0[5] = fmaf(cv0, vb.y, o0[5]);
            o0[6] = fmaf(cv0, vb.z, o0[6]); o0[7] = fmaf(cv0, vb.w, o0[7]);
            o1[0] = fmaf(cv1, va.x, o1[0]); o1[1] = fmaf(cv1, va.y, o1[1]);
            o1[2] = fmaf(cv1, va.z, o1[2]); o1[3] = fmaf(cv1, va.w, o1[3]);
            o1[4] = fmaf(cv1, vb.x, o1[4]); o1[5] = fmaf(cv1, vb.y, o1[5]);
            o1[6] = fmaf(cv1, vb.z, o1[6]); o1[7] = fmaf(cv1, vb.w, o1[7]);
        }
        float* dst0 = g_att + (size_t)(bid * 64 + r0) * CDIM + h * 64 + t8 * 8;
        *reinterpret_cast<float4*>(dst0)     = make_float4(o0[0], o0[1], o0[2], o0[3]);
        *reinterpret_cast<float4*>(dst0 + 4) = make_float4(o0[4], o0[5], o0[6], o0[7]);
        float* dst1 = dst0 + CDIM;
        *reinterpret_cast<float4*>(dst1)     = make_float4(o1[0], o1[1], o1[2], o1[3]);
        *reinterpret_cast<float4*>(dst1 + 4) = make_float4(o1[4], o1[5], o1[6], o1[7]);
    }
}

// ================= host =================
extern "C" void kernel_launch(void* const* d_in, const int* in_sizes, int n_in,
                              void* d_out, int out_size) {
    (void)in_sizes; (void)n_in; (void)out_size;
    const float* x      = (const float*)d_in[0];
    const int*   amask  = (const int*)d_in[1];
    const float* edge   = (const float*)d_in[2];
    const float* qkv_w  = (const float*)d_in[3];
    const float* qkv_b  = (const float*)d_in[4];
    const float* proj_w = (const float*)d_in[5];
    const float* proj_b = (const float*)d_in[6];
    const float* eg_w   = (const float*)d_in[7];
    const float* eg_b   = (const float*)d_in[8];
    float* out = (float*)d_out;

    cudaFuncSetAttribute(attn_kernel, cudaFuncAttributeMaxDynamicSharedMemorySize, ATTN_SMEM_BYTES);

    mean_kernel<<<BNB, 256>>>(x);
    gemm_tf32<0><<<dim3(MX / 128, 1536 / 128), 256>>>(x, qkv_w, qkv_b, nullptr);
    gemm_tf32<1><<<dim3(BNB / 128, 1024 / 128), 256>>>(nullptr, qkv_w + (size_t)512 * 512, qkv_b + 512, nullptr);
    attn_kernel<<<BNB, 256, ATTN_SMEM_BYTES>>>(edge, amask, eg_w, eg_b);
    gemm_tf32<2><<<dim3(MX / 128, 512 / 128), 256>>>(nullptr, proj_w, proj_b, out);
}

// round 2
// speedup vs baseline: 1.1375x; 1.1375x over previous
#include <cuda_runtime.h>
#include <cstdint>

#define NB_B   2
#define NB     512
#define LQ     64
#define KEYN   65
#define NH     8
#define HD     64
#define CDIM   512
#define NTOK   32768
#define BNB    (NB_B*NB)        // 1024 blocks total
#define MX     (NB_B*NTOK)      // 65536 x-rows
#define KVROWS (BNB*KEYN)       // 66560 kv-rows

// -------- device scratch (static, allocation-guard safe) --------
__device__ float g_q  [(size_t)MX*CDIM];
__device__ float g_k  [(size_t)KVROWS*CDIM];
__device__ float g_v  [(size_t)KVROWS*CDIM];
__device__ float g_bm [(size_t)BNB*CDIM];
__device__ float g_att[(size_t)MX*CDIM];
__device__ float g_biasadd[(size_t)BNB*4160];
__device__ float g_lew[(size_t)BNB*NH*4160];

// ================= block mean =================
__global__ void mean_kernel(const float* __restrict__ x) {
    int blk = blockIdx.x;                      // 0..1023 (b*512+nb)
    const float* base = x + (size_t)blk * (LQ * CDIM);
    for (int c = threadIdx.x; c < CDIM; c += blockDim.x) {
        float s = 0.f;
        #pragma unroll 8
        for (int l = 0; l < LQ; l++) s += base[(size_t)l * CDIM + c];
        g_bm[(size_t)blk * CDIM + c] = s * (1.f / 64.f);
    }
}

// ================= prep: fold mask into bias, precompute lew =================
__global__ void __launch_bounds__(256) prep_kernel(const float* __restrict__ edge,
                                                   const int* __restrict__ amask,
                                                   const float* __restrict__ eg_w,
                                                   const float* __restrict__ eg_b) {
    int bid = blockIdx.x;
    const float4* e4 = reinterpret_cast<const float4*>(edge) + (size_t)bid * 4160;
    const int* mk = amask + (size_t)bid * 4160;
    float w[NH][4], b[NH];
    #pragma unroll
    for (int h = 0; h < NH; h++) {
        w[h][0] = eg_w[h * 4 + 0]; w[h][1] = eg_w[h * 4 + 1];
        w[h][2] = eg_w[h * 4 + 2]; w[h][3] = eg_w[h * 4 + 3];
        b[h] = eg_b[h];
    }
    for (int i = threadIdx.x; i < 4160; i += 256) {
        int q = i / 65;
        int k = i - q * 65;
        float4 e = e4[i];
        if (k == 64 || k == q) e = make_float4(0.f, 0.f, 0.f, 1.f);
        bool m = (mk[i] != 0);
        g_biasadd[(size_t)bid * 4160 + i] = m ? e.w : -1e30f;
        #pragma unroll
        for (int h = 0; h < NH; h++) {
            float lv = e.x * w[h][0] + e.y * w[h][1] + e.z * w[h][2] + e.w * w[h][3] + b[h];
            g_lew[((size_t)bid * NH + h) * 4160 + i] = m ? lv : 0.f;
        }
    }
}

// ================= tf32 mma helpers =================
__device__ __forceinline__ float to_tf32(float x) {
    uint32_t u;
    asm("cvt.rna.tf32.f32 %0, %1;" : "=r"(u) : "f"(x));
    return __uint_as_float(u);
}

__device__ __forceinline__ void mma_tf32(float* c, const float* a, const float* b) {
    const uint32_t* A = reinterpret_cast<const uint32_t*>(a);
    const uint32_t* Bv = reinterpret_cast<const uint32_t*>(b);
    asm volatile(
        "mma.sync.aligned.m16n8k8.row.col.f32.tf32.tf32.f32 "
        "{%0,%1,%2,%3}, {%4,%5,%6,%7}, {%8,%9}, {%0,%1,%2,%3};\n"
        : "+f"(c[0]), "+f"(c[1]), "+f"(c[2]), "+f"(c[3])
        : "r"(A[0]), "r"(A[1]), "r"(A[2]), "r"(A[3]),
          "r"(Bv[0]), "r"(Bv[1]));
}

// epilogue scatter
template <int MODE>
__device__ __forceinline__ void emit(int row, int col, float v, float* outp) {
    if (MODE == 0) {
        if (col < CDIM) {
            g_q[(size_t)row * CDIM + col] = v;
        } else {
            size_t kvr = (size_t)((row >> 6) * KEYN + (row & 63));
            if (col < 2 * CDIM) g_k[kvr * CDIM + (col - CDIM)] = v;
            else                g_v[kvr * CDIM + (col - 2 * CDIM)] = v;
        }
    } else if (MODE == 1) {
        size_t r = (size_t)row * KEYN + (KEYN - 1);
        if (col < CDIM) g_k[r * CDIM + col] = v;
        else            g_v[r * CDIM + (col - CDIM)] = v;
    } else {
        outp[(size_t)row * CDIM + col] = v;
    }
}

// ================= tf32 GEMM: C = A[M,512] * W[N,512]^T + bias =================
// 128x128x32 tiles, 256 threads = 8 warps (2x4), warp tile 64x32, mma m16n8k8
template <int MODE>
__global__ void __launch_bounds__(256) gemm_tf32(const float* __restrict__ Ain,
                                                 const float* __restrict__ W,
                                                 const float* __restrict__ bias,
                                                 float* __restrict__ outp) {
    const float* A = (MODE == 1) ? g_bm : (MODE == 2 ? g_att : Ain);
    __shared__ float As[128][36];
    __shared__ float Bs[128][36];

    int tid = threadIdx.x;
    int m0 = blockIdx.x * 128;
    int n0 = blockIdx.y * 128;
    int lr = tid >> 3;          // 0..31
    int lc = (tid & 7) * 4;     // 0..28

    int lane = tid & 31, wid = tid >> 5;
    int wm = wid >> 2, wn = wid & 3;   // warp grid 2 x 4
    int g = lane >> 2, t4 = lane & 3;

    float acc[4][4][4];
    #pragma unroll
    for (int mi = 0; mi < 4; mi++)
        #pragma unroll
        for (int ni = 0; ni < 4; ni++)
            #pragma unroll
            for (int r = 0; r < 4; r++) acc[mi][ni][r] = 0.f;

    float4 ra[4], rb[4];
    {
        #pragma unroll
        for (int i = 0; i < 4; i++) {
            ra[i] = *reinterpret_cast<const float4*>(&A[(size_t)(m0 + lr + 32 * i) * CDIM + 0 + lc]);
            rb[i] = *reinterpret_cast<const float4*>(&W[(size_t)(n0 + lr + 32 * i) * CDIM + 0 + lc]);
        }
    }

    for (int k0 = 0; k0 < CDIM; k0 += 32) {
        __syncthreads();
        #pragma unroll
        for (int i = 0; i < 4; i++) {
            float4 ta = make_float4(to_tf32(ra[i].x), to_tf32(ra[i].y), to_tf32(ra[i].z), to_tf32(ra[i].w));
            float4 tb = make_float4(to_tf32(rb[i].x), to_tf32(rb[i].y), to_tf32(rb[i].z), to_tf32(rb[i].w));
            *reinterpret_cast<float4*>(&As[lr + 32 * i][lc]) = ta;
            *reinterpret_cast<float4*>(&Bs[lr + 32 * i][lc]) = tb;
        }
        __syncthreads();
        if (k0 + 32 < CDIM) {
            #pragma unroll
            for (int i = 0; i < 4; i++) {
                ra[i] = *reinterpret_cast<const float4*>(&A[(size_t)(m0 + lr + 32 * i) * CDIM + (k0 + 32) + lc]);
                rb[i] = *reinterpret_cast<const float4*>(&W[(size_t)(n0 + lr + 32 * i) * CDIM + (k0 + 32) + lc]);
            }
        }
        #pragma unroll
        for (int kk = 0; kk < 32; kk += 8) {
            float afr[4][4], bfr[4][2];
            #pragma unroll
            for (int mi = 0; mi < 4; mi++) {
                int row = wm * 64 + mi * 16 + g;
                afr[mi][0] = As[row][kk + t4];
                afr[mi][1] = As[row + 8][kk + t4];
                afr[mi][2] = As[row][kk + t4 + 4];
                afr[mi][3] = As[row + 8][kk + t4 + 4];
            }
            #pragma unroll
            for (int ni = 0; ni < 4; ni++) {
                int col = wn * 32 + ni * 8 + g;
                bfr[ni][0] = Bs[col][kk + t4];
                bfr[ni][1] = Bs[col][kk + t4 + 4];
            }
            #pragma unroll
            for (int mi = 0; mi < 4; mi++)
                #pragma unroll
                for (int ni = 0; ni < 4; ni++)
                    mma_tf32(acc[mi][ni], afr[mi], bfr[ni]);
        }
    }

    // epilogue
    #pragma unroll
    for (int mi = 0; mi < 4; mi++) {
        #pragma unroll
        for (int ni = 0; ni < 4; ni++) {
            int row = m0 + wm * 64 + mi * 16 + g;
            int col = n0 + wn * 32 + ni * 8 + t4 * 2;
            float b0 = bias[col], b1 = bias[col + 1];
            emit<MODE>(row,     col,     acc[mi][ni][0] + b0, outp);
            emit<MODE>(row,     col + 1, acc[mi][ni][1] + b1, outp);
            emit<MODE>(row + 8, col,     acc[mi][ni][2] + b0, outp);
            emit<MODE>(row + 8, col + 1, acc[mi][ni][3] + b1, outp);
        }
    }
}

// ================= attention =================
// one CTA per (b, blk): 256 threads, loop over 8 heads
// smem floats: biasadd 4160 | q 64*68 | k 72*68 | v 65*68 | comb 64*68
#define SM_Q_OFF    4160
#define SM_K_OFF    (SM_Q_OFF + 64 * 68)
#define SM_V_OFF    (SM_K_OFF + 72 * 68)
#define SM_CB_OFF   (SM_V_OFF + 65 * 68)
#define ATTN_SMEM_FLOATS (SM_CB_OFF + 64 * 68)
#define ATTN_SMEM_BYTES  (ATTN_SMEM_FLOATS * 4)   // ~88.7 KB -> 2 CTAs/SM

__global__ void __launch_bounds__(256, 2) attn_kernel() {
    extern __shared__ float sm[];
    float* ba_s = sm;                     // 4160 pre-masked additive bias
    float* q_s = sm + SM_Q_OFF;
    float* k_s = sm + SM_K_OFF;
    float* v_s = sm + SM_V_OFF;
    float* cb_s = sm + SM_CB_OFF;

    int bid = blockIdx.x;      // 0..1023
    int tid = threadIdx.x;

    for (int i = tid; i < 4160; i += 256)
        ba_s[i] = g_biasadd[(size_t)bid * 4160 + i];
    // zero-pad k rows 65..71 (read by cols>=65 lanes, results discarded)
    for (int i = tid; i < 7 * 68; i += 256) k_s[65 * 68 + i] = 0.f;

    int lane = tid & 31, warp = tid >> 5;
    int t8 = lane & 7, g2 = lane >> 3;
    int r0 = warp * 8 + g2 * 2;          // this lane handles rows r0, r0+1

    for (int h = 0; h < NH; h++) {
        __syncthreads();
        // load q/k/v head slices
        for (int f = tid; f < 64 * 16; f += 256) {
            int row = f >> 4, c4 = (f & 15) * 4;
            *reinterpret_cast<float4*>(&q_s[row * 68 + c4]) =
                *reinterpret_cast<const float4*>(&g_q[(size_t)(bid * 64 + row) * CDIM + h * 64 + c4]);
        }
        for (int f = tid; f < 65 * 16; f += 256) {
            int row = f / 16, c4 = (f & 15) * 4;
            size_t src = (size_t)(bid * 65 + row) * CDIM + h * 64 + c4;
            *reinterpret_cast<float4*>(&k_s[row * 68 + c4]) =
                *reinterpret_cast<const float4*>(&g_k[src]);
            *reinterpret_cast<float4*>(&v_s[row * 68 + c4]) =
                *reinterpret_cast<const float4*>(&g_v[src]);
        }
        __syncthreads();

        const float* lew_g = g_lew + ((size_t)bid * NH + h) * 4160;

        // ---- scores: rows r0,r0+1 x cols {t8+8j} ----
        float acc0[9], acc1[9];
        #pragma unroll
        for (int j = 0; j < 9; j++) { acc0[j] = 0.f; acc1[j] = 0.f; }
        #pragma unroll 4
        for (int d4 = 0; d4 < 16; d4++) {
            float4 qa = *reinterpret_cast<const float4*>(&q_s[r0 * 68 + d4 * 4]);
            float4 qb = *reinterpret_cast<const float4*>(&q_s[(r0 + 1) * 68 + d4 * 4]);
            #pragma unroll
            for (int j = 0; j < 9; j++) {
                float4 kv = *reinterpret_cast<const float4*>(&k_s[(t8 + 8 * j) * 68 + d4 * 4]);
                acc0[j] = fmaf(qa.x, kv.x, acc0[j]);
                acc0[j] = fmaf(qa.y, kv.y, acc0[j]);
                acc0[j] = fmaf(qa.z, kv.z, acc0[j]);
                acc0[j] = fmaf(qa.w, kv.w, acc0[j]);
                acc1[j] = fmaf(qb.x, kv.x, acc1[j]);
                acc1[j] = fmaf(qb.y, kv.y, acc1[j]);
                acc1[j] = fmaf(qb.z, kv.z, acc1[j]);
                acc1[j] = fmaf(qb.w, kv.w, acc1[j]);
            }
        }

        // ---- masked softmax + lew, write combined to smem ----
        #pragma unroll
        for (int rr = 0; rr < 2; rr++) {
            float* acc = rr ? acc1 : acc0;
            int row = r0 + rr;
            float mx = -1e30f;
            #pragma unroll
            for (int j = 0; j < 9; j++) {
                int col = t8 + 8 * j;
                if (col < 65) {
                    float s = acc[j] * 0.125f + ba_s[row * 65 + col];
                    acc[j] = s;
                    mx = fmaxf(mx, s);
                } else {
                    acc[j] = -3e30f;
                }
            }
            mx = fmaxf(mx, __shfl_xor_sync(0xffffffffu, mx, 1));
            mx = fmaxf(mx, __shfl_xor_sync(0xffffffffu, mx, 2));
            mx = fmaxf(mx, __shfl_xor_sync(0xffffffffu, mx, 4));
            float sum = 0.f;
            #pragma unroll
            for (int j = 0; j < 9; j++) {
                float p = __expf(acc[j] - mx);
                acc[j] = p;
                sum += p;
            }
            sum += __shfl_xor_sync(0xffffffffu, sum, 1);
            sum += __shfl_xor_sync(0xffffffffu, sum, 2);
            sum += __shfl_xor_sync(0xffffffffu, sum, 4);
            float inv = 1.f / sum;
            #pragma unroll
            for (int j = 0; j < 9; j++) {
                int col = t8 + 8 * j;
                if (col < 65) {
                    int idx = row * 65 + col;
                    cb_s[row * 68 + col] = acc[j] * inv + __ldg(&lew_g[idx]);
                }
            }
        }
        __syncwarp();

        // ---- AV: out[row, d in t8*8 .. t8*8+7] ----
        float o0[8], o1[8];
        #pragma unroll
        for (int j = 0; j < 8; j++) { o0[j] = 0.f; o1[j] = 0.f; }
        for (int k = 0; k < 65; k++) {
            float cv0 = cb_s[r0 * 68 + k];
            float cv1 = cb_s[(r0 + 1) * 68 + k];
            float4 va = *reinterpret_cast<const float4*>(&v_s[k * 68 + t8 * 8]);
            float4 vb = *reinterpret_cast<const float4*>(&v_s[k * 68 + t8 * 8 + 4]);
            o0[0] = fmaf(cv0, va.x, o0[0]); o0[1] = fmaf(cv0, va.y, o0[1]);
            o0[2] = fmaf(cv0, va.z, o0[2]); o0[3] = fmaf(cv0, va.w, o0[3]);
            o0[4] = fmaf(cv0, vb.x, o0[4]); o0[5] = fmaf(cv0, vb.y, o0[5]);
            o0[6] = fmaf(cv0, vb.z, o0[6]); o0[7] = fmaf(cv0, vb.w, o0[7]);
            o1[0] = fmaf(cv1, va.x, o1[0]); o1[1] = fmaf(cv1, va.y, o1[1]);
            o1[2] = fmaf(cv1, va.z, o1[2]); o1[3] = fmaf(cv1, va.w, o1[3]);
            o1[4] = fmaf(cv1, vb.x, o1[4]); o1[5] = fmaf(cv1, vb.y, o1[5]);
            o1[6] = fmaf(cv1, vb.z, o1[6]); o1[7] = fmaf(cv1, vb.w, o1[7]);
        }
        float* dst0 = g_att + (size_t)(bid * 64 + r0) * CDIM + h * 64 + t8 * 8;
        *reinterpret_cast<float4*>(dst0)     = make_float4(o0[0], o0[1], o0[2], o0[3]);
        *reinterpret_cast<float4*>(dst0 + 4) = make_float4(o0[4], o0[5], o0[6], o0[7]);
        float* dst1 = dst0 + CDIM;
        *reinterpret_cast<float4*>(dst1)     = make_float4(o1[0], o1[1], o1[2], o1[3]);
        *reinterpret_cast<float4*>(dst1 + 4) = make_float4(o1[4], o1[5], o1[6], o1[7]);
    }
}

// ================= host =================
extern "C" void kernel_launch(void* const* d_in, const int* in_sizes, int n_in,
                              void* d_out, int out_size) {
    (void)in_sizes; (void)n_in; (void)out_size;
    const float* x      = (const float*)d_in[0];
    const int*   amask  = (const int*)d_in[1];
    const float* edge   = (const float*)d_in[2];
    const float* qkv_w  = (const float*)d_in[3];
    const float* qkv_b  = (const float*)d_in[4];
    const float* proj_w = (const float*)d_in[5];
    const float* proj_b = (const float*)d_in[6];
    const float* eg_w   = (const float*)d_in[7];
    const float* eg_b   = (const float*)d_in[8];
    float* out = (float*)d_out;

    cudaFuncSetAttribute(attn_kernel, cudaFuncAttributeMaxDynamicSharedMemorySize, ATTN_SMEM_BYTES);

    mean_kernel<<<BNB, 256>>>(x);
    prep_kernel<<<BNB, 256>>>(edge, amask, eg_w, eg_b);
    gemm_tf32<0><<<dim3(MX / 128, 1536 / 128), 256>>>(x, qkv_w, qkv_b, nullptr);
    gemm_tf32<1><<<dim3(BNB / 128, 1024 / 128), 256>>>(nullptr, qkv_w + (size_t)512 * 512, qkv_b + 512, nullptr);
    attn_kernel<<<BNB, 256, ATTN_SMEM_BYTES>>>();
    gemm_tf32<2><<<dim3(MX / 128, 512 / 128), 256>>>(nullptr, proj_w, proj_b, out);
}